// round 2
// baseline (speedup 1.0000x reference)
#include <cuda_runtime.h>
#include <cuda_fp16.h>
#include <cstdint>

// ---------------------------------------------------------------------------
// GCN_simple: out = meanpool(relu(gcn2(relu(gcn1(x))))) @ (W3@Wlin) + (b3@Wlin+blin)
// Graph structure is fixed: only nodes 0..127 (graph 0) have edges; all other
// nodes see identity propagation. Layer3+pool collapse exactly (sum-preserving).
// ---------------------------------------------------------------------------

#define NROWS 65536      // BATCH * N_NODES
#define KDIM  512
#define NDIM  512
#define NGRAPH 512
#define GSIZE  128       // nodes per graph
#define OUTD   10

#define BM 128
#define BN 128
#define BK 32
#define STAGES 3
#define ALD (BK + 8)     // 40 halves
#define BLD (BN + 8)     // 136 halves
#define ASTAGE (BM * ALD)   // halves per A stage
#define BSTAGE (BK * BLD)   // halves per B stage

// ------------------------------- scratch (device globals; no cudaMalloc) ----
__device__ __half g_Xh[(size_t)NROWS * KDIM];   // fp16 copy of x
__device__ __half g_H1[(size_t)NROWS * KDIM];   // layer-1 activations
__device__ __half g_W1h[KDIM * NDIM];
__device__ __half g_W2h[KDIM * NDIM];
__device__ float  g_pool[NGRAPH * NDIM];        // per-graph column sums of h2
__device__ float  g_L1[GSIZE * NDIM];           // raw x@W1 rows 0..127
__device__ float  g_L2[GSIZE * NDIM];           // raw h1@W2 rows 0..127
__device__ float  g_Wc[KDIM * OUTD];            // W3 @ Wlin
__device__ float  g_bc[OUTD];                   // b3 @ Wlin + blin

// ------------------------------- small helpers ------------------------------
__device__ __forceinline__ void cpasync16(void* smem_ptr, const void* gmem_ptr) {
    uint32_t s = (uint32_t)__cvta_generic_to_shared(smem_ptr);
    asm volatile("cp.async.cg.shared.global [%0], [%1], 16;\n" :: "r"(s), "l"(gmem_ptr));
}
__device__ __forceinline__ void cp_commit() {
    asm volatile("cp.async.commit_group;\n" ::: "memory");
}
__device__ __forceinline__ void cp_wait1() {
    asm volatile("cp.async.wait_group 1;\n" ::: "memory");
}
__device__ __forceinline__ void mma16816(float& c0, float& c1, float& c2, float& c3,
                                         uint32_t a0, uint32_t a1, uint32_t a2, uint32_t a3,
                                         uint32_t b0, uint32_t b1) {
    asm volatile(
        "mma.sync.aligned.m16n8k16.row.col.f32.f16.f16.f32 "
        "{%0,%1,%2,%3}, {%4,%5,%6,%7}, {%8,%9}, {%0,%1,%2,%3};\n"
        : "+f"(c0), "+f"(c1), "+f"(c2), "+f"(c3)
        : "r"(a0), "r"(a1), "r"(a2), "r"(a3), "r"(b0), "r"(b1));
}
__device__ __forceinline__ uint32_t pack_half2(__half lo, __half hi) {
    __half2 h = __halves2half2(lo, hi);
    return *reinterpret_cast<uint32_t*>(&h);
}

// ------------------------------- conversion kernels -------------------------
__global__ void conv_x_kernel(const float* __restrict__ x) {
    size_t i = ((size_t)blockIdx.x * blockDim.x + threadIdx.x) * 4;
    if (i < (size_t)NROWS * KDIM) {
        float4 v = *reinterpret_cast<const float4*>(x + i);
        *reinterpret_cast<__half2*>(g_Xh + i)     = __floats2half2_rn(v.x, v.y);
        *reinterpret_cast<__half2*>(g_Xh + i + 2) = __floats2half2_rn(v.z, v.w);
    }
}

__global__ void conv_w_kernel(const float* __restrict__ w1, const float* __restrict__ w2) {
    size_t i = ((size_t)blockIdx.x * blockDim.x + threadIdx.x) * 4;
    if (i < (size_t)KDIM * NDIM) {
        float4 v = *reinterpret_cast<const float4*>(w1 + i);
        *reinterpret_cast<__half2*>(g_W1h + i)     = __floats2half2_rn(v.x, v.y);
        *reinterpret_cast<__half2*>(g_W1h + i + 2) = __floats2half2_rn(v.z, v.w);
        float4 u = *reinterpret_cast<const float4*>(w2 + i);
        *reinterpret_cast<__half2*>(g_W2h + i)     = __floats2half2_rn(u.x, u.y);
        *reinterpret_cast<__half2*>(g_W2h + i + 2) = __floats2half2_rn(u.z, u.w);
    }
}

// Wc = W3 @ Wlin   (512 x 10)
__global__ void wc_kernel(const float* __restrict__ W3, const float* __restrict__ Wlin) {
    int k = blockIdx.x;                 // 0..511
    int c = threadIdx.x >> 5;           // 0..9  (block = 320)
    int lane = threadIdx.x & 31;
    float a = 0.f;
    for (int j = lane; j < KDIM; j += 32)
        a += W3[k * KDIM + j] * Wlin[j * OUTD + c];
    #pragma unroll
    for (int o = 16; o; o >>= 1) a += __shfl_xor_sync(0xffffffffu, a, o);
    if (lane == 0) g_Wc[k * OUTD + c] = a;
}

// bc = b3 @ Wlin + blin
__global__ void bc_kernel(const float* __restrict__ b3, const float* __restrict__ Wlin,
                          const float* __restrict__ blin) {
    int c = threadIdx.x >> 5;           // block = 320
    int lane = threadIdx.x & 31;
    float a = 0.f;
    for (int k = lane; k < KDIM; k += 32)
        a += b3[k] * Wlin[k * OUTD + c];
    #pragma unroll
    for (int o = 16; o; o >>= 1) a += __shfl_xor_sync(0xffffffffu, a, o);
    if (lane == 0) g_bc[c] = a + blin[c];
}

// ------------------------------- main GEMMs ---------------------------------
// MODE 1: H1 = relu(Xh @ W1h + b1)  (store fp16); row-tile 0 also stores raw acc.
// MODE 2: pool[g] = colsum(relu(H1 @ W2h + b2)) per tile; row-tile 0 stores raw acc.
template <int MODE>
__global__ void __launch_bounds__(256) gemm_kernel(const float* __restrict__ bias) {
    extern __shared__ __half smem[];
    __half* As = smem;                       // STAGES * ASTAGE
    __half* Bs = smem + STAGES * ASTAGE;     // STAGES * BSTAGE

    const __half* __restrict__ A = (MODE == 1) ? g_Xh : g_H1;
    const __half* __restrict__ B = (MODE == 1) ? g_W1h : g_W2h;

    const int tid  = threadIdx.x;
    const int lane = tid & 31;
    const int warp = tid >> 5;
    const int wm = warp >> 2;                // 0..1
    const int wn = warp & 3;                 // 0..3
    const int mtile = blockIdx.y;
    const int ntile = blockIdx.x;
    const size_t mbase = (size_t)mtile * BM;
    const int nbase = ntile * BN;

    float acc[4][4][4];
    #pragma unroll
    for (int a = 0; a < 4; ++a)
        #pragma unroll
        for (int b = 0; b < 4; ++b)
            #pragma unroll
            for (int c = 0; c < 4; ++c) acc[a][b][c] = 0.f;

    auto load_stage = [&](int s, int kt) {
        const int k0 = kt * BK;
        #pragma unroll
        for (int c = 0; c < 2; ++c) {
            int id = tid + c * 256;
            int ar = id >> 2, akc = id & 3;                       // A: 128 rows x 4 chunks
            cpasync16(As + s * ASTAGE + ar * ALD + akc * 8,
                      A + (mbase + ar) * KDIM + k0 + akc * 8);
            int br = id >> 4, bnc = id & 15;                      // B: 32 rows x 16 chunks
            cpasync16(Bs + s * BSTAGE + br * BLD + bnc * 8,
                      B + (size_t)(k0 + br) * NDIM + nbase + bnc * 8);
        }
    };

    auto compute = [&](int s) {
        const __half* Ab = As + s * ASTAGE;
        const __half* Bb = Bs + s * BSTAGE;
        #pragma unroll
        for (int ks = 0; ks < 2; ++ks) {
            const int k0 = ks * 16 + (lane & 3) * 2;
            uint32_t af[4][4];
            #pragma unroll
            for (int mi = 0; mi < 4; ++mi) {
                int m0 = wm * 64 + mi * 16 + (lane >> 2);
                af[mi][0] = *reinterpret_cast<const uint32_t*>(Ab + m0 * ALD + k0);
                af[mi][1] = *reinterpret_cast<const uint32_t*>(Ab + (m0 + 8) * ALD + k0);
                af[mi][2] = *reinterpret_cast<const uint32_t*>(Ab + m0 * ALD + k0 + 8);
                af[mi][3] = *reinterpret_cast<const uint32_t*>(Ab + (m0 + 8) * ALD + k0 + 8);
            }
            uint32_t bf[4][2];
            #pragma unroll
            for (int ni = 0; ni < 4; ++ni) {
                int n0 = wn * 32 + ni * 8 + (lane >> 2);
                bf[ni][0] = pack_half2(Bb[k0 * BLD + n0], Bb[(k0 + 1) * BLD + n0]);
                bf[ni][1] = pack_half2(Bb[(k0 + 8) * BLD + n0], Bb[(k0 + 9) * BLD + n0]);
            }
            #pragma unroll
            for (int mi = 0; mi < 4; ++mi)
                #pragma unroll
                for (int ni = 0; ni < 4; ++ni)
                    mma16816(acc[mi][ni][0], acc[mi][ni][1], acc[mi][ni][2], acc[mi][ni][3],
                             af[mi][0], af[mi][1], af[mi][2], af[mi][3],
                             bf[ni][0], bf[ni][1]);
        }
    };

    const int KTILES = KDIM / BK;   // 16
    load_stage(0, 0); cp_commit();
    load_stage(1, 1); cp_commit();

    for (int kt = 0; kt < KTILES; ++kt) {
        cp_wait1();
        __syncthreads();
        if (kt + 2 < KTILES) load_stage((kt + 2) % 3, kt + 2);
        cp_commit();
        compute(kt % 3);
    }

    // ------------------------------ epilogue --------------------------------
    if (MODE == 1) {
        #pragma unroll
        for (int mi = 0; mi < 4; ++mi) {
            int r0 = wm * 64 + mi * 16 + (lane >> 2);
            #pragma unroll
            for (int ni = 0; ni < 4; ++ni) {
                int c0 = wn * 32 + ni * 8 + ((lane & 3) << 1);
                int gc = nbase + c0;
                if (mtile == 0) {
                    g_L1[r0 * NDIM + gc]           = acc[mi][ni][0];
                    g_L1[r0 * NDIM + gc + 1]       = acc[mi][ni][1];
                    g_L1[(r0 + 8) * NDIM + gc]     = acc[mi][ni][2];
                    g_L1[(r0 + 8) * NDIM + gc + 1] = acc[mi][ni][3];
                }
                float bb0 = bias[gc], bb1 = bias[gc + 1];
                float v0 = fmaxf(acc[mi][ni][0] + bb0, 0.f);
                float v1 = fmaxf(acc[mi][ni][1] + bb1, 0.f);
                float v2 = fmaxf(acc[mi][ni][2] + bb0, 0.f);
                float v3 = fmaxf(acc[mi][ni][3] + bb1, 0.f);
                *reinterpret_cast<__half2*>(g_H1 + (mbase + r0) * NDIM + gc)     = __floats2half2_rn(v0, v1);
                *reinterpret_cast<__half2*>(g_H1 + (mbase + r0 + 8) * NDIM + gc) = __floats2half2_rn(v2, v3);
            }
        }
    } else {
        // column-sum of relu(acc + b2) over the 128 rows of this tile (= one graph)
        float cs0[4], cs1[4];
        #pragma unroll
        for (int ni = 0; ni < 4; ++ni) { cs0[ni] = 0.f; cs1[ni] = 0.f; }
        #pragma unroll
        for (int mi = 0; mi < 4; ++mi) {
            int r0 = wm * 64 + mi * 16 + (lane >> 2);
            #pragma unroll
            for (int ni = 0; ni < 4; ++ni) {
                int c0 = wn * 32 + ni * 8 + ((lane & 3) << 1);
                int gc = nbase + c0;
                if (mtile == 0) {
                    g_L2[r0 * NDIM + gc]           = acc[mi][ni][0];
                    g_L2[r0 * NDIM + gc + 1]       = acc[mi][ni][1];
                    g_L2[(r0 + 8) * NDIM + gc]     = acc[mi][ni][2];
                    g_L2[(r0 + 8) * NDIM + gc + 1] = acc[mi][ni][3];
                }
                float bb0 = bias[gc], bb1 = bias[gc + 1];
                cs0[ni] += fmaxf(acc[mi][ni][0] + bb0, 0.f) + fmaxf(acc[mi][ni][2] + bb0, 0.f);
                cs1[ni] += fmaxf(acc[mi][ni][1] + bb1, 0.f) + fmaxf(acc[mi][ni][3] + bb1, 0.f);
            }
        }
        // reduce over the 8 lanes sharing (lane & 3)
        #pragma unroll
        for (int ni = 0; ni < 4; ++ni) {
            #pragma unroll
            for (int o = 4; o <= 16; o <<= 1) {
                cs0[ni] += __shfl_xor_sync(0xffffffffu, cs0[ni], o);
                cs1[ni] += __shfl_xor_sync(0xffffffffu, cs1[ni], o);
            }
        }
        __syncthreads();                       // pipeline smem no longer needed
        float* cs = reinterpret_cast<float*>(smem);   // BN floats
        if (tid < BN) cs[tid] = 0.f;
        __syncthreads();
        if ((lane >> 2) == 0) {                // lanes 0..3 of each warp
            #pragma unroll
            for (int ni = 0; ni < 4; ++ni) {
                int c0 = wn * 32 + ni * 8 + ((lane & 3) << 1);
                atomicAdd(&cs[c0],     cs0[ni]);
                atomicAdd(&cs[c0 + 1], cs1[ni]);
            }
        }
        __syncthreads();
        if (tid < BN) g_pool[(size_t)mtile * NDIM + nbase + tid] = cs[tid];
    }
}

// ------------------------------- graph-0 fixups -----------------------------
__global__ void fixup1_kernel(const float* __restrict__ b1) {
    int c = threadIdx.x;                 // 512 threads
    float S = 0.f;
    #pragma unroll 8
    for (int r = 0; r < GSIZE; ++r) S += g_L1[r * NDIM + c];
    float bv = b1[c];
    #pragma unroll 8
    for (int r = 0; r < GSIZE; ++r) {
        float v = (S + g_L1[r * NDIM + c]) * (1.f / 129.f) + bv;
        g_H1[(size_t)r * NDIM + c] = __float2half(v > 0.f ? v : 0.f);
    }
}

__global__ void fixup2_kernel(const float* __restrict__ b2) {
    int c = threadIdx.x;                 // 512 threads
    float S = 0.f;
    #pragma unroll 8
    for (int r = 0; r < GSIZE; ++r) S += g_L2[r * NDIM + c];
    float bv = b2[c], p = 0.f;
    #pragma unroll 8
    for (int r = 0; r < GSIZE; ++r) {
        float v = (S + g_L2[r * NDIM + c]) * (1.f / 129.f) + bv;
        p += (v > 0.f ? v : 0.f);
    }
    g_pool[c] = p;                       // overwrite graph-0 pooled sums
}

// ------------------------------- final projection ---------------------------
__global__ void final_kernel(float* __restrict__ out) {
    int g = blockIdx.x;                  // 0..511
    int c = threadIdx.x >> 5;            // 0..9  (block = 320)
    int lane = threadIdx.x & 31;
    float a = 0.f;
    for (int k = lane; k < KDIM; k += 32)
        a += g_pool[(size_t)g * NDIM + k] * g_Wc[k * OUTD + c];
    #pragma unroll
    for (int o = 16; o; o >>= 1) a += __shfl_xor_sync(0xffffffffu, a, o);
    if (lane == 0) out[g * OUTD + c] = a * (1.f / (float)GSIZE) + g_bc[c];
}

// ------------------------------- launch -------------------------------------
extern "C" void kernel_launch(void* const* d_in, const int* in_sizes, int n_in,
                              void* d_out, int out_size) {
    const float* x    = (const float*)d_in[0];
    const float* W1   = (const float*)d_in[1];
    const float* b1   = (const float*)d_in[2];
    const float* W2   = (const float*)d_in[3];
    const float* b2   = (const float*)d_in[4];
    const float* W3   = (const float*)d_in[5];
    const float* b3   = (const float*)d_in[6];
    const float* Wlin = (const float*)d_in[7];
    const float* blin = (const float*)d_in[8];
    float* out = (float*)d_out;

    const size_t smem_bytes = (size_t)STAGES * (ASTAGE + BSTAGE) * sizeof(__half); // 56832
    cudaFuncSetAttribute(gemm_kernel<1>, cudaFuncAttributeMaxDynamicSharedMemorySize, (int)smem_bytes);
    cudaFuncSetAttribute(gemm_kernel<2>, cudaFuncAttributeMaxDynamicSharedMemorySize, (int)smem_bytes);

    conv_x_kernel<<<(NROWS * (size_t)KDIM) / (256 * 4), 256>>>(x);
    conv_w_kernel<<<(KDIM * NDIM) / (256 * 4), 256>>>(W1, W2);
    wc_kernel<<<KDIM, 320>>>(W3, Wlin);
    bc_kernel<<<1, 320>>>(b3, Wlin, blin);

    dim3 grid(NDIM / BN, NROWS / BM);    // (4, 512)
    gemm_kernel<1><<<grid, 256, smem_bytes>>>(b1);
    fixup1_kernel<<<1, NDIM>>>(b1);
    gemm_kernel<2><<<grid, 256, smem_bytes>>>(b2);
    fixup2_kernel<<<1, NDIM>>>(b2);
    final_kernel<<<NGRAPH, 320>>>(out);
}

// round 5
// speedup vs baseline: 1.0977x; 1.0977x over previous
#include <cuda_runtime.h>
#include <cuda_fp16.h>
#include <cstdint>

// ---------------------------------------------------------------------------
// GCN_simple: layer3+meanpool collapse analytically; layers 1-2 are dense
// GEMMs (identity propagation except graph 0, fixed up separately).
// mma.sync HMMA pipeline (tcgen05 PTX rejected by this toolchain's compute_103
// virtual target). GEMM1 fuses the fp32->fp16 conversion of x; weights are
// pre-transposed to [n][k] so every fragment load is one 32-bit LDS.
// ---------------------------------------------------------------------------

#define NROWS 65536      // BATCH * N_NODES
#define KDIM  512
#define NDIM  512
#define NGRAPH 512
#define GSIZE  128
#define OUTD   10

#define BM 128
#define BN 128
#define BK 32
#define KTILES (KDIM / BK)   // 16
#define ALDF 40              // fp32 A row pitch (floats)  — MODE 1
#define ALDH 40              // fp16 A row pitch (halves)  — MODE 2
#define BLDH 40              // fp16 B row pitch (halves), B stored [n][k]

#define ASTG_F (BM * ALDF)          // floats per A stage (MODE 1)
#define ASTG_H (BM * ALDH)          // halves per A stage (MODE 2)
#define BSTG_H (BN * BLDH)          // halves per B stage
#define STAGE1_BYTES (ASTG_F * 4 + BSTG_H * 2)   // 30720
#define STAGE2_BYTES (ASTG_H * 2 + BSTG_H * 2)   // 20480
#define SMEM1 (3 * STAGE1_BYTES)    // 92160
#define SMEM2 (3 * STAGE2_BYTES)    // 61440

// ------------------------------- device scratch -----------------------------
__device__ __half g_H1[(size_t)NROWS * KDIM];
__device__ __half g_W1t[KDIM * NDIM];   // W1^T: [n][k] fp16
__device__ __half g_W2t[KDIM * NDIM];
__device__ float  g_pool[NGRAPH * NDIM];
__device__ float  g_L1[GSIZE * NDIM];
__device__ float  g_L2[GSIZE * NDIM];
__device__ float  g_Wc[KDIM * OUTD];
__device__ float  g_bc[OUTD];

// ------------------------------- helpers ------------------------------------
__device__ __forceinline__ void cpasync16(void* smem_ptr, const void* gmem_ptr) {
    uint32_t s = (uint32_t)__cvta_generic_to_shared(smem_ptr);
    asm volatile("cp.async.cg.shared.global [%0], [%1], 16;\n" :: "r"(s), "l"(gmem_ptr));
}
__device__ __forceinline__ void cp_commit() {
    asm volatile("cp.async.commit_group;\n" ::: "memory");
}
__device__ __forceinline__ void cp_wait1() {
    asm volatile("cp.async.wait_group 1;\n" ::: "memory");
}
__device__ __forceinline__ void mma16816(float& c0, float& c1, float& c2, float& c3,
                                         uint32_t a0, uint32_t a1, uint32_t a2, uint32_t a3,
                                         uint32_t b0, uint32_t b1) {
    asm volatile(
        "mma.sync.aligned.m16n8k16.row.col.f32.f16.f16.f32 "
        "{%0,%1,%2,%3}, {%4,%5,%6,%7}, {%8,%9}, {%0,%1,%2,%3};\n"
        : "+f"(c0), "+f"(c1), "+f"(c2), "+f"(c3)
        : "r"(a0), "r"(a1), "r"(a2), "r"(a3), "r"(b0), "r"(b1));
}
__device__ __forceinline__ uint32_t cvt_h2(float lo, float hi) {
    __half2 h = __floats2half2_rn(lo, hi);
    return *reinterpret_cast<uint32_t*>(&h);
}

// ------------------------------- setup kernels ------------------------------
// out[n][k] = (half) W[k][n]
__global__ void convT_w_kernel(const float* __restrict__ W, int which) {
    __shared__ float t[32][33];
    __half* out = which ? g_W2t : g_W1t;
    int bx = blockIdx.x * 32, by = blockIdx.y * 32;
    #pragma unroll
    for (int i = 0; i < 32; i += 8)
        t[threadIdx.y + i][threadIdx.x] = W[(size_t)(by + threadIdx.y + i) * NDIM + bx + threadIdx.x];
    __syncthreads();
    #pragma unroll
    for (int i = 0; i < 32; i += 8)
        out[(size_t)(bx + threadIdx.y + i) * KDIM + by + threadIdx.x] =
            __float2half(t[threadIdx.x][threadIdx.y + i]);
}

__global__ void wc_kernel(const float* __restrict__ W3, const float* __restrict__ Wlin) {
    int k = blockIdx.x, c = threadIdx.x >> 5, lane = threadIdx.x & 31;
    float a = 0.f;
    for (int j = lane; j < KDIM; j += 32) a += W3[k * KDIM + j] * Wlin[j * OUTD + c];
    #pragma unroll
    for (int o = 16; o; o >>= 1) a += __shfl_xor_sync(0xffffffffu, a, o);
    if (lane == 0) g_Wc[k * OUTD + c] = a;
}

__global__ void bc_kernel(const float* __restrict__ b3, const float* __restrict__ Wlin,
                          const float* __restrict__ blin) {
    int c = threadIdx.x >> 5, lane = threadIdx.x & 31;
    float a = 0.f;
    for (int k = lane; k < KDIM; k += 32) a += b3[k] * Wlin[k * OUTD + c];
    #pragma unroll
    for (int o = 16; o; o >>= 1) a += __shfl_xor_sync(0xffffffffu, a, o);
    if (lane == 0) g_bc[c] = a + blin[c];
}

// ------------------------------- main GEMMs ---------------------------------
// MODE 1: H1 = relu(x @ W1 + b1), x fp32 converted in-flight; mtile 0 -> g_L1.
// MODE 2: pool[g] = colsum(relu(H1 @ W2 + b2)); mtile 0 raw acc -> g_L2.
template <int MODE>
__global__ void __launch_bounds__(256, 2) gemm_kernel(const float* __restrict__ Afp32,
                                                      const float* __restrict__ bias) {
    extern __shared__ char smem[];
    const int tid  = threadIdx.x;
    const int lane = tid & 31;
    const int warp = tid >> 5;
    const int wm = warp >> 2;                // 0..1
    const int wn = warp & 3;                 // 0..3
    const int ntile = blockIdx.x;
    const int mtile = blockIdx.y;
    const size_t mbase = (size_t)mtile * BM;
    const int nbase = ntile * BN;

    const __half* __restrict__ Bt = (MODE == 1) ? g_W1t : g_W2t;

    float acc[4][4][4];
    #pragma unroll
    for (int a = 0; a < 4; ++a)
        #pragma unroll
        for (int b = 0; b < 4; ++b)
            #pragma unroll
            for (int c = 0; c < 4; ++c) acc[a][b][c] = 0.f;

    const int stage_bytes = (MODE == 1) ? STAGE1_BYTES : STAGE2_BYTES;
    const int a_bytes     = (MODE == 1) ? ASTG_F * 4 : ASTG_H * 2;

    auto load_stage = [&](int s, int kt) {
        const int k0 = kt * BK;
        char* as = smem + s * stage_bytes;
        char* bs = as + a_bytes;
        if (MODE == 1) {
            // A: 128 rows x 32 fp32 -> 8 chunks of 16B per row (1024 loads)
            #pragma unroll
            for (int i = 0; i < 4; ++i) {
                int id = tid + 256 * i;
                int row = id >> 3, ch = id & 7;
                cpasync16(as + (row * ALDF + ch * 4) * 4,
                          Afp32 + (mbase + row) * KDIM + k0 + ch * 4);
            }
        } else {
            // A: 128 rows x 32 fp16 -> 4 chunks of 16B per row (512 loads)
            #pragma unroll
            for (int i = 0; i < 2; ++i) {
                int id = tid + 256 * i;
                int row = id >> 2, ch = id & 3;
                cpasync16(as + (row * ALDH + ch * 8) * 2,
                          g_H1 + (mbase + row) * KDIM + k0 + ch * 8);
            }
        }
        // B: 128 n-rows x 32 k fp16 (512 loads)
        #pragma unroll
        for (int i = 0; i < 2; ++i) {
            int id = tid + 256 * i;
            int row = id >> 2, ch = id & 3;
            cpasync16(bs + (row * BLDH + ch * 8) * 2,
                      Bt + (size_t)(nbase + row) * KDIM + k0 + ch * 8);
        }
    };

    auto compute = [&](int s) {
        const char* as = smem + s * stage_bytes;
        const __half* bs = reinterpret_cast<const __half*>(as + a_bytes);
        #pragma unroll
        for (int ks = 0; ks < 2; ++ks) {
            const int k0 = ks * 16 + (lane & 3) * 2;
            uint32_t af[4][4];
            #pragma unroll
            for (int mi = 0; mi < 4; ++mi) {
                int m0 = wm * 64 + mi * 16 + (lane >> 2);
                if (MODE == 1) {
                    const float* af32 = reinterpret_cast<const float*>(as);
                    float2 p0 = *reinterpret_cast<const float2*>(af32 + m0 * ALDF + k0);
                    float2 p1 = *reinterpret_cast<const float2*>(af32 + (m0 + 8) * ALDF + k0);
                    float2 p2 = *reinterpret_cast<const float2*>(af32 + m0 * ALDF + k0 + 8);
                    float2 p3 = *reinterpret_cast<const float2*>(af32 + (m0 + 8) * ALDF + k0 + 8);
                    af[mi][0] = cvt_h2(p0.x, p0.y);
                    af[mi][1] = cvt_h2(p1.x, p1.y);
                    af[mi][2] = cvt_h2(p2.x, p2.y);
                    af[mi][3] = cvt_h2(p3.x, p3.y);
                } else {
                    const __half* ah = reinterpret_cast<const __half*>(as);
                    af[mi][0] = *reinterpret_cast<const uint32_t*>(ah + m0 * ALDH + k0);
                    af[mi][1] = *reinterpret_cast<const uint32_t*>(ah + (m0 + 8) * ALDH + k0);
                    af[mi][2] = *reinterpret_cast<const uint32_t*>(ah + m0 * ALDH + k0 + 8);
                    af[mi][3] = *reinterpret_cast<const uint32_t*>(ah + (m0 + 8) * ALDH + k0 + 8);
                }
            }
            uint32_t bf[4][2];
            #pragma unroll
            for (int ni = 0; ni < 4; ++ni) {
                int n0 = wn * 32 + ni * 8 + (lane >> 2);
                bf[ni][0] = *reinterpret_cast<const uint32_t*>(bs + n0 * BLDH + k0);
                bf[ni][1] = *reinterpret_cast<const uint32_t*>(bs + n0 * BLDH + k0 + 8);
            }
            #pragma unroll
            for (int mi = 0; mi < 4; ++mi)
                #pragma unroll
                for (int ni = 0; ni < 4; ++ni)
                    mma16816(acc[mi][ni][0], acc[mi][ni][1], acc[mi][ni][2], acc[mi][ni][3],
                             af[mi][0], af[mi][1], af[mi][2], af[mi][3],
                             bf[ni][0], bf[ni][1]);
        }
    };

    load_stage(0, 0); cp_commit();
    load_stage(1, 1); cp_commit();

    for (int kt = 0; kt < KTILES; ++kt) {
        cp_wait1();
        __syncthreads();
        if (kt + 2 < KTILES) load_stage((kt + 2) % 3, kt + 2);
        cp_commit();
        compute(kt % 3);
    }

    // ------------------------------ epilogue --------------------------------
    if (MODE == 1) {
        #pragma unroll
        for (int mi = 0; mi < 4; ++mi) {
            int r0 = wm * 64 + mi * 16 + (lane >> 2);
            #pragma unroll
            for (int ni = 0; ni < 4; ++ni) {
                int c0 = wn * 32 + ni * 8 + ((lane & 3) << 1);
                int gc = nbase + c0;
                if (mtile == 0) {
                    g_L1[r0 * NDIM + gc]           = acc[mi][ni][0];
                    g_L1[r0 * NDIM + gc + 1]       = acc[mi][ni][1];
                    g_L1[(r0 + 8) * NDIM + gc]     = acc[mi][ni][2];
                    g_L1[(r0 + 8) * NDIM + gc + 1] = acc[mi][ni][3];
                }
                float bb0 = bias[gc], bb1 = bias[gc + 1];
                float v0 = fmaxf(acc[mi][ni][0] + bb0, 0.f);
                float v1 = fmaxf(acc[mi][ni][1] + bb1, 0.f);
                float v2 = fmaxf(acc[mi][ni][2] + bb0, 0.f);
                float v3 = fmaxf(acc[mi][ni][3] + bb1, 0.f);
                *reinterpret_cast<__half2*>(g_H1 + (mbase + r0) * NDIM + gc)     = __floats2half2_rn(v0, v1);
                *reinterpret_cast<__half2*>(g_H1 + (mbase + r0 + 8) * NDIM + gc) = __floats2half2_rn(v2, v3);
            }
        }
    } else {
        float cs0[4], cs1[4];
        #pragma unroll
        for (int ni = 0; ni < 4; ++ni) { cs0[ni] = 0.f; cs1[ni] = 0.f; }
        #pragma unroll
        for (int mi = 0; mi < 4; ++mi) {
            int r0 = wm * 64 + mi * 16 + (lane >> 2);
            #pragma unroll
            for (int ni = 0; ni < 4; ++ni) {
                int c0 = wn * 32 + ni * 8 + ((lane & 3) << 1);
                int gc = nbase + c0;
                if (mtile == 0) {
                    g_L2[r0 * NDIM + gc]           = acc[mi][ni][0];
                    g_L2[r0 * NDIM + gc + 1]       = acc[mi][ni][1];
                    g_L2[(r0 + 8) * NDIM + gc]     = acc[mi][ni][2];
                    g_L2[(r0 + 8) * NDIM + gc + 1] = acc[mi][ni][3];
                }
                float bb0 = bias[gc], bb1 = bias[gc + 1];
                cs0[ni] += fmaxf(acc[mi][ni][0] + bb0, 0.f) + fmaxf(acc[mi][ni][2] + bb0, 0.f);
                cs1[ni] += fmaxf(acc[mi][ni][1] + bb1, 0.f) + fmaxf(acc[mi][ni][3] + bb1, 0.f);
            }
        }
        #pragma unroll
        for (int ni = 0; ni < 4; ++ni) {
            #pragma unroll
            for (int o = 4; o <= 16; o <<= 1) {
                cs0[ni] += __shfl_xor_sync(0xffffffffu, cs0[ni], o);
                cs1[ni] += __shfl_xor_sync(0xffffffffu, cs1[ni], o);
            }
        }
        __syncthreads();
        float* cs = reinterpret_cast<float*>(smem);
        if (tid < BN) cs[tid] = 0.f;
        __syncthreads();
        if ((lane >> 2) == 0) {
            #pragma unroll
            for (int ni = 0; ni < 4; ++ni) {
                int c0 = wn * 32 + ni * 8 + ((lane & 3) << 1);
                atomicAdd(&cs[c0],     cs0[ni]);
                atomicAdd(&cs[c0 + 1], cs1[ni]);
            }
        }
        __syncthreads();
        if (tid < BN) g_pool[(size_t)mtile * NDIM + nbase + tid] = cs[tid];
    }
}

// ------------------------------- graph-0 fixups -----------------------------
__global__ void fixup1_kernel(const float* __restrict__ b1) {
    int c = threadIdx.x;
    float S = 0.f;
    #pragma unroll 8
    for (int r = 0; r < GSIZE; ++r) S += g_L1[r * NDIM + c];
    float bv = b1[c];
    #pragma unroll 8
    for (int r = 0; r < GSIZE; ++r) {
        float v = (S + g_L1[r * NDIM + c]) * (1.f / 129.f) + bv;
        g_H1[(size_t)r * NDIM + c] = __float2half(v > 0.f ? v : 0.f);
    }
}

__global__ void fixup2_kernel(const float* __restrict__ b2) {
    int c = threadIdx.x;
    float S = 0.f;
    #pragma unroll 8
    for (int r = 0; r < GSIZE; ++r) S += g_L2[r * NDIM + c];
    float bv = b2[c], p = 0.f;
    #pragma unroll 8
    for (int r = 0; r < GSIZE; ++r) {
        float v = (S + g_L2[r * NDIM + c]) * (1.f / 129.f) + bv;
        p += (v > 0.f ? v : 0.f);
    }
    g_pool[c] = p;
}

// ------------------------------- final projection ---------------------------
__global__ void final_kernel(float* __restrict__ out) {
    int g = blockIdx.x, c = threadIdx.x >> 5, lane = threadIdx.x & 31;
    float a = 0.f;
    for (int k = lane; k < KDIM; k += 32)
        a += g_pool[(size_t)g * NDIM + k] * g_Wc[k * OUTD + c];
    #pragma unroll
    for (int o = 16; o; o >>= 1) a += __shfl_xor_sync(0xffffffffu, a, o);
    if (lane == 0) out[g * OUTD + c] = a * (1.f / (float)GSIZE) + g_bc[c];
}

// ------------------------------- launch -------------------------------------
extern "C" void kernel_launch(void* const* d_in, const int* in_sizes, int n_in,
                              void* d_out, int out_size) {
    const float* x    = (const float*)d_in[0];
    const float* W1   = (const float*)d_in[1];
    const float* b1   = (const float*)d_in[2];
    const float* W2   = (const float*)d_in[3];
    const float* b2   = (const float*)d_in[4];
    const float* W3   = (const float*)d_in[5];
    const float* b3   = (const float*)d_in[6];
    const float* Wlin = (const float*)d_in[7];
    const float* blin = (const float*)d_in[8];
    float* out = (float*)d_out;

    cudaFuncSetAttribute(gemm_kernel<1>, cudaFuncAttributeMaxDynamicSharedMemorySize, SMEM1);
    cudaFuncSetAttribute(gemm_kernel<2>, cudaFuncAttributeMaxDynamicSharedMemorySize, SMEM2);

    dim3 grid(NDIM / BN, NROWS / BM);    // (4, 512)

    convT_w_kernel<<<dim3(16, 16), dim3(32, 8)>>>(W1, 0);      // 1
    convT_w_kernel<<<dim3(16, 16), dim3(32, 8)>>>(W2, 1);      // 2
    gemm_kernel<1><<<grid, 256, SMEM1>>>(x, b1);               // 3
    fixup1_kernel<<<1, NDIM>>>(b1);                            // 4
    bc_kernel<<<1, 320>>>(b3, Wlin, blin);                     // 5
    gemm_kernel<2><<<grid, 256, SMEM2>>>(nullptr, b2);         // 6  <- ncu -s 5
    wc_kernel<<<KDIM, 320>>>(W3, Wlin);                        // 7
    fixup2_kernel<<<1, NDIM>>>(b2);                            // 8
    final_kernel<<<NGRAPH, 320>>>(out);                        // 9
}

// round 6
// speedup vs baseline: 1.1961x; 1.0896x over previous
#include <cuda_runtime.h>
#include <cuda_fp16.h>
#include <cstdint>

// ---------------------------------------------------------------------------
// GCN_simple: layer3+meanpool collapse analytically; layers 1-2 are dense
// GEMMs (identity propagation except graph 0, fixed up by parallel fixups).
// mma.sync HMMA pipeline (tcgen05 unavailable: virtual target compute_103
// rejects it). GEMM1 converts fp32 x in-flight; weights pre-transposed [n][k];
// fp16 fragment loads via ldmatrix.x4.
// ---------------------------------------------------------------------------

#define NROWS 65536      // BATCH * N_NODES
#define KDIM  512
#define NDIM  512
#define NGRAPH 512
#define GSIZE  128
#define OUTD   10

#define BM 128
#define BN 128
#define BK 32
#define KTILES (KDIM / BK)   // 16
#define ALDF 40              // fp32 A row pitch (floats)  — MODE 1
#define ALDH 40              // fp16 A row pitch (halves)  — MODE 2
#define BLDH 40              // fp16 B row pitch (halves), B stored [n][k]

#define ASTG_F (BM * ALDF)
#define ASTG_H (BM * ALDH)
#define BSTG_H (BN * BLDH)
#define STAGE1_BYTES (ASTG_F * 4 + BSTG_H * 2)   // 30720
#define STAGE2_BYTES (ASTG_H * 2 + BSTG_H * 2)   // 20480
#define SMEM1 (3 * STAGE1_BYTES)    // 92160
#define SMEM2 (3 * STAGE2_BYTES)    // 61440

// ------------------------------- device scratch -----------------------------
__device__ __half g_H1[(size_t)NROWS * KDIM];
__device__ __half g_W1t[KDIM * NDIM];   // W1^T: [n][k] fp16
__device__ __half g_W2t[KDIM * NDIM];
__device__ float  g_pool[NGRAPH * NDIM];
__device__ float  g_L1[GSIZE * NDIM];
__device__ float  g_L2[GSIZE * NDIM];
__device__ float  g_Wc[KDIM * OUTD];
__device__ float  g_bc[OUTD];

// ------------------------------- helpers ------------------------------------
__device__ __forceinline__ void cpasync16(void* smem_ptr, const void* gmem_ptr) {
    uint32_t s = (uint32_t)__cvta_generic_to_shared(smem_ptr);
    asm volatile("cp.async.cg.shared.global [%0], [%1], 16;\n" :: "r"(s), "l"(gmem_ptr));
}
__device__ __forceinline__ void cp_commit() {
    asm volatile("cp.async.commit_group;\n" ::: "memory");
}
__device__ __forceinline__ void cp_wait1() {
    asm volatile("cp.async.wait_group 1;\n" ::: "memory");
}
__device__ __forceinline__ void mma16816(float& c0, float& c1, float& c2, float& c3,
                                         uint32_t a0, uint32_t a1, uint32_t a2, uint32_t a3,
                                         uint32_t b0, uint32_t b1) {
    asm volatile(
        "mma.sync.aligned.m16n8k16.row.col.f32.f16.f16.f32 "
        "{%0,%1,%2,%3}, {%4,%5,%6,%7}, {%8,%9}, {%0,%1,%2,%3};\n"
        : "+f"(c0), "+f"(c1), "+f"(c2), "+f"(c3)
        : "r"(a0), "r"(a1), "r"(a2), "r"(a3), "r"(b0), "r"(b1));
}
__device__ __forceinline__ void ldsm_x4(uint32_t& r0, uint32_t& r1, uint32_t& r2, uint32_t& r3,
                                        uint32_t saddr) {
    asm volatile("ldmatrix.sync.aligned.m8n8.x4.shared.b16 {%0,%1,%2,%3}, [%4];"
                 : "=r"(r0), "=r"(r1), "=r"(r2), "=r"(r3) : "r"(saddr));
}
__device__ __forceinline__ uint32_t smem_u32(const void* p) {
    return (uint32_t)__cvta_generic_to_shared(p);
}
__device__ __forceinline__ uint32_t cvt_h2(float lo, float hi) {
    __half2 h = __floats2half2_rn(lo, hi);
    return *reinterpret_cast<uint32_t*>(&h);
}

// ------------------------------- setup kernels ------------------------------
// out[n][k] = (half) W[k][n]
__global__ void convT_w_kernel(const float* __restrict__ W, int which) {
    __shared__ float t[32][33];
    __half* out = which ? g_W2t : g_W1t;
    int bx = blockIdx.x * 32, by = blockIdx.y * 32;
    #pragma unroll
    for (int i = 0; i < 32; i += 8)
        t[threadIdx.y + i][threadIdx.x] = W[(size_t)(by + threadIdx.y + i) * NDIM + bx + threadIdx.x];
    __syncthreads();
    #pragma unroll
    for (int i = 0; i < 32; i += 8)
        out[(size_t)(bx + threadIdx.y + i) * KDIM + by + threadIdx.x] =
            __float2half(t[threadIdx.x][threadIdx.y + i]);
}

__global__ void wc_kernel(const float* __restrict__ W3, const float* __restrict__ Wlin) {
    int k = blockIdx.x, c = threadIdx.x >> 5, lane = threadIdx.x & 31;
    float a = 0.f;
    for (int j = lane; j < KDIM; j += 32) a += W3[k * KDIM + j] * Wlin[j * OUTD + c];
    #pragma unroll
    for (int o = 16; o; o >>= 1) a += __shfl_xor_sync(0xffffffffu, a, o);
    if (lane == 0) g_Wc[k * OUTD + c] = a;
}

__global__ void bc_kernel(const float* __restrict__ b3, const float* __restrict__ Wlin,
                          const float* __restrict__ blin) {
    int c = threadIdx.x >> 5, lane = threadIdx.x & 31;
    float a = 0.f;
    for (int k = lane; k < KDIM; k += 32) a += b3[k] * Wlin[k * OUTD + c];
    #pragma unroll
    for (int o = 16; o; o >>= 1) a += __shfl_xor_sync(0xffffffffu, a, o);
    if (lane == 0) g_bc[c] = a + blin[c];
}

// ------------------------------- main GEMMs ---------------------------------
// MODE 1: H1 = relu(x @ W1 + b1), x fp32 converted in-flight; mtile 0 -> g_L1.
// MODE 2: pool[g] = colsum(relu(H1 @ W2 + b2)); mtile 0 raw acc -> g_L2.
template <int MODE>
__global__ void __launch_bounds__(256, 2) gemm_kernel(const float* __restrict__ Afp32,
                                                      const float* __restrict__ bias) {
    extern __shared__ char smem[];
    const int tid  = threadIdx.x;
    const int lane = tid & 31;
    const int warp = tid >> 5;
    const int wm = warp >> 2;                // 0..1
    const int wn = warp & 3;                 // 0..3
    const int ntile = blockIdx.x;
    const int mtile = blockIdx.y;
    const size_t mbase = (size_t)mtile * BM;
    const int nbase = ntile * BN;

    const __half* __restrict__ Bt = (MODE == 1) ? g_W1t : g_W2t;

    float acc[4][4][4];
    #pragma unroll
    for (int a = 0; a < 4; ++a)
        #pragma unroll
        for (int b = 0; b < 4; ++b)
            #pragma unroll
            for (int c = 0; c < 4; ++c) acc[a][b][c] = 0.f;

    const int stage_bytes = (MODE == 1) ? STAGE1_BYTES : STAGE2_BYTES;
    const int a_bytes     = (MODE == 1) ? ASTG_F * 4 : ASTG_H * 2;

    // per-thread ldmatrix source geometry
    const int lrow = lane & 15;              // row within 16-row tile
    const int lkof = (lane >> 4) * 8;        // 0 or 8 halves (k offset)

    auto load_stage = [&](int s, int kt) {
        const int k0 = kt * BK;
        char* as = smem + s * stage_bytes;
        char* bs = as + a_bytes;
        if (MODE == 1) {
            #pragma unroll
            for (int i = 0; i < 4; ++i) {
                int id = tid + 256 * i;
                int row = id >> 3, ch = id & 7;
                cpasync16(as + (row * ALDF + ch * 4) * 4,
                          Afp32 + (mbase + row) * KDIM + k0 + ch * 4);
            }
        } else {
            #pragma unroll
            for (int i = 0; i < 2; ++i) {
                int id = tid + 256 * i;
                int row = id >> 2, ch = id & 3;
                cpasync16(as + (row * ALDH + ch * 8) * 2,
                          g_H1 + (mbase + row) * KDIM + k0 + ch * 8);
            }
        }
        #pragma unroll
        for (int i = 0; i < 2; ++i) {
            int id = tid + 256 * i;
            int row = id >> 2, ch = id & 3;
            cpasync16(bs + (row * BLDH + ch * 8) * 2,
                      Bt + (size_t)(nbase + row) * KDIM + k0 + ch * 8);
        }
    };

    auto compute = [&](int s) {
        const char* as = smem + s * stage_bytes;
        const __half* bs = reinterpret_cast<const __half*>(as + a_bytes);
        const uint32_t b_u32 = smem_u32(bs);
        const uint32_t a_u32 = smem_u32(as);
        #pragma unroll
        for (int ks = 0; ks < 2; ++ks) {
            const int kh = ks * 16;          // k base (halves)
            uint32_t af[4][4];
            if (MODE == 1) {
                const int k0 = kh + (lane & 3) * 2;
                const float* af32 = reinterpret_cast<const float*>(as);
                #pragma unroll
                for (int mi = 0; mi < 4; ++mi) {
                    int m0 = wm * 64 + mi * 16 + (lane >> 2);
                    float2 p0 = *reinterpret_cast<const float2*>(af32 + m0 * ALDF + k0);
                    float2 p1 = *reinterpret_cast<const float2*>(af32 + (m0 + 8) * ALDF + k0);
                    float2 p2 = *reinterpret_cast<const float2*>(af32 + m0 * ALDF + k0 + 8);
                    float2 p3 = *reinterpret_cast<const float2*>(af32 + (m0 + 8) * ALDF + k0 + 8);
                    af[mi][0] = cvt_h2(p0.x, p0.y);
                    af[mi][1] = cvt_h2(p1.x, p1.y);
                    af[mi][2] = cvt_h2(p2.x, p2.y);
                    af[mi][3] = cvt_h2(p3.x, p3.y);
                }
            } else {
                #pragma unroll
                for (int mi = 0; mi < 4; ++mi) {
                    int row = wm * 64 + mi * 16 + lrow;
                    uint32_t addr = a_u32 + (row * ALDH + kh + lkof) * 2;
                    ldsm_x4(af[mi][0], af[mi][1], af[mi][2], af[mi][3], addr);
                }
            }
            uint32_t bf[4][2];
            #pragma unroll
            for (int np = 0; np < 2; ++np) {   // pairs of ni
                int row = wn * 32 + np * 16 + lrow;
                uint32_t addr = b_u32 + (row * BLDH + kh + lkof) * 2;
                ldsm_x4(bf[2 * np][0], bf[2 * np + 1][0],
                        bf[2 * np][1], bf[2 * np + 1][1], addr);
            }
            #pragma unroll
            for (int mi = 0; mi < 4; ++mi)
                #pragma unroll
                for (int ni = 0; ni < 4; ++ni)
                    mma16816(acc[mi][ni][0], acc[mi][ni][1], acc[mi][ni][2], acc[mi][ni][3],
                             af[mi][0], af[mi][1], af[mi][2], af[mi][3],
                             bf[ni][0], bf[ni][1]);
        }
    };

    load_stage(0, 0); cp_commit();
    load_stage(1, 1); cp_commit();

    for (int kt = 0; kt < KTILES; ++kt) {
        cp_wait1();
        __syncthreads();
        if (kt + 2 < KTILES) load_stage((kt + 2) % 3, kt + 2);
        cp_commit();
        compute(kt % 3);
    }

    // ------------------------------ epilogue --------------------------------
    if (MODE == 1) {
        #pragma unroll
        for (int mi = 0; mi < 4; ++mi) {
            int r0 = wm * 64 + mi * 16 + (lane >> 2);
            #pragma unroll
            for (int ni = 0; ni < 4; ++ni) {
                int c0 = wn * 32 + ni * 8 + ((lane & 3) << 1);
                int gc = nbase + c0;
                if (mtile == 0) {
                    g_L1[r0 * NDIM + gc]           = acc[mi][ni][0];
                    g_L1[r0 * NDIM + gc + 1]       = acc[mi][ni][1];
                    g_L1[(r0 + 8) * NDIM + gc]     = acc[mi][ni][2];
                    g_L1[(r0 + 8) * NDIM + gc + 1] = acc[mi][ni][3];
                }
                float bb0 = bias[gc], bb1 = bias[gc + 1];
                float v0 = fmaxf(acc[mi][ni][0] + bb0, 0.f);
                float v1 = fmaxf(acc[mi][ni][1] + bb1, 0.f);
                float v2 = fmaxf(acc[mi][ni][2] + bb0, 0.f);
                float v3 = fmaxf(acc[mi][ni][3] + bb1, 0.f);
                *reinterpret_cast<__half2*>(g_H1 + (mbase + r0) * NDIM + gc)     = __floats2half2_rn(v0, v1);
                *reinterpret_cast<__half2*>(g_H1 + (mbase + r0 + 8) * NDIM + gc) = __floats2half2_rn(v2, v3);
            }
        }
    } else {
        float cs0[4], cs1[4];
        #pragma unroll
        for (int ni = 0; ni < 4; ++ni) { cs0[ni] = 0.f; cs1[ni] = 0.f; }
        #pragma unroll
        for (int mi = 0; mi < 4; ++mi) {
            int r0 = wm * 64 + mi * 16 + (lane >> 2);
            #pragma unroll
            for (int ni = 0; ni < 4; ++ni) {
                int c0 = wn * 32 + ni * 8 + ((lane & 3) << 1);
                int gc = nbase + c0;
                if (mtile == 0) {
                    g_L2[r0 * NDIM + gc]           = acc[mi][ni][0];
                    g_L2[r0 * NDIM + gc + 1]       = acc[mi][ni][1];
                    g_L2[(r0 + 8) * NDIM + gc]     = acc[mi][ni][2];
                    g_L2[(r0 + 8) * NDIM + gc + 1] = acc[mi][ni][3];
                }
                float bb0 = bias[gc], bb1 = bias[gc + 1];
                cs0[ni] += fmaxf(acc[mi][ni][0] + bb0, 0.f) + fmaxf(acc[mi][ni][2] + bb0, 0.f);
                cs1[ni] += fmaxf(acc[mi][ni][1] + bb1, 0.f) + fmaxf(acc[mi][ni][3] + bb1, 0.f);
            }
        }
        #pragma unroll
        for (int ni = 0; ni < 4; ++ni) {
            #pragma unroll
            for (int o = 4; o <= 16; o <<= 1) {
                cs0[ni] += __shfl_xor_sync(0xffffffffu, cs0[ni], o);
                cs1[ni] += __shfl_xor_sync(0xffffffffu, cs1[ni], o);
            }
        }
        __syncthreads();
        float* cs = reinterpret_cast<float*>(smem);
        if (tid < BN) cs[tid] = 0.f;
        __syncthreads();
        if ((lane >> 2) == 0) {
            #pragma unroll
            for (int ni = 0; ni < 4; ++ni) {
                int c0 = wn * 32 + ni * 8 + ((lane & 3) << 1);
                atomicAdd(&cs[c0],     cs0[ni]);
                atomicAdd(&cs[c0 + 1], cs1[ni]);
            }
        }
        __syncthreads();
        if (tid < BN) g_pool[(size_t)mtile * NDIM + nbase + tid] = cs[tid];
    }
}

// ------------------------------- graph-0 fixups (parallel) ------------------
__global__ void fixup1_kernel(const float* __restrict__ b1) {
    int c = blockIdx.x;                  // 512 columns
    int r = threadIdx.x;                 // 128 rows
    float v = g_L1[r * NDIM + c];
    __shared__ float sred[4];
    float s = v;
    #pragma unroll
    for (int o = 16; o; o >>= 1) s += __shfl_xor_sync(0xffffffffu, s, o);
    if ((r & 31) == 0) sred[r >> 5] = s;
    __syncthreads();
    float S = sred[0] + sred[1] + sred[2] + sred[3];
    float out = (S + v) * (1.f / 129.f) + b1[c];
    g_H1[(size_t)r * NDIM + c] = __float2half(out > 0.f ? out : 0.f);
}

__global__ void fixup2_kernel(const float* __restrict__ b2) {
    int c = blockIdx.x;
    int r = threadIdx.x;
    float v = g_L2[r * NDIM + c];
    __shared__ float sred[4];
    float s = v;
    #pragma unroll
    for (int o = 16; o; o >>= 1) s += __shfl_xor_sync(0xffffffffu, s, o);
    if ((r & 31) == 0) sred[r >> 5] = s;
    __syncthreads();
    float S = sred[0] + sred[1] + sred[2] + sred[3];
    float val = (S + v) * (1.f / 129.f) + b2[c];
    float rel = val > 0.f ? val : 0.f;
    // reduce relu'd values over rows -> pooled sum for graph 0
    #pragma unroll
    for (int o = 16; o; o >>= 1) rel += __shfl_xor_sync(0xffffffffu, rel, o);
    if ((r & 31) == 0) sred[r >> 5] = rel;
    __syncthreads();
    if (r == 0) g_pool[c] = sred[0] + sred[1] + sred[2] + sred[3];
}

// ------------------------------- final projection ---------------------------
__global__ void final_kernel(float* __restrict__ out) {
    int g = blockIdx.x, c = threadIdx.x >> 5, lane = threadIdx.x & 31;
    float a = 0.f;
    for (int k = lane; k < KDIM; k += 32)
        a += g_pool[(size_t)g * NDIM + k] * g_Wc[k * OUTD + c];
    #pragma unroll
    for (int o = 16; o; o >>= 1) a += __shfl_xor_sync(0xffffffffu, a, o);
    if (lane == 0) out[g * OUTD + c] = a * (1.f / (float)GSIZE) + g_bc[c];
}

// ------------------------------- launch -------------------------------------
extern "C" void kernel_launch(void* const* d_in, const int* in_sizes, int n_in,
                              void* d_out, int out_size) {
    const float* x    = (const float*)d_in[0];
    const float* W1   = (const float*)d_in[1];
    const float* b1   = (const float*)d_in[2];
    const float* W2   = (const float*)d_in[3];
    const float* b2   = (const float*)d_in[4];
    const float* W3   = (const float*)d_in[5];
    const float* b3   = (const float*)d_in[6];
    const float* Wlin = (const float*)d_in[7];
    const float* blin = (const float*)d_in[8];
    float* out = (float*)d_out;

    cudaFuncSetAttribute(gemm_kernel<1>, cudaFuncAttributeMaxDynamicSharedMemorySize, SMEM1);
    cudaFuncSetAttribute(gemm_kernel<2>, cudaFuncAttributeMaxDynamicSharedMemorySize, SMEM2);

    dim3 grid(NDIM / BN, NROWS / BM);    // (4, 512)

    convT_w_kernel<<<dim3(16, 16), dim3(32, 8)>>>(W1, 0);      // 1
    convT_w_kernel<<<dim3(16, 16), dim3(32, 8)>>>(W2, 1);      // 2
    bc_kernel<<<1, 320>>>(b3, Wlin, blin);                     // 3
    gemm_kernel<1><<<grid, 256, SMEM1>>>(x, b1);               // 4  <- ncu lands here
    fixup1_kernel<<<NDIM, GSIZE>>>(b1);                        // 5
    gemm_kernel<2><<<grid, 256, SMEM2>>>(nullptr, b2);         // 6
    wc_kernel<<<KDIM, 320>>>(W3, Wlin);                        // 7
    fixup2_kernel<<<NDIM, GSIZE>>>(b2);                        // 8
    final_kernel<<<NGRAPH, 320>>>(out);                        // 9
}

// round 8
// speedup vs baseline: 1.2389x; 1.0358x over previous
#include <cuda_runtime.h>
#include <cuda_fp16.h>
#include <cstdint>

// ---------------------------------------------------------------------------
// GCN_simple: layer3+meanpool collapse analytically; layers 1-2 are dense
// GEMMs (identity propagation except graph 0, fixed by parallel fixups).
// mma.sync HMMA pipeline (tcgen05 rejected by compute_103 virtual target).
// Both GEMMs: fp16 smem, BK=64, 3-stage cp.async, ldmatrix.x4 fragments.
// ---------------------------------------------------------------------------

#define NROWS 65536      // BATCH * N_NODES
#define KDIM  512
#define NDIM  512
#define NGRAPH 512
#define GSIZE  128
#define OUTD   10

#define BM 128
#define BN 128
#define BK 64
#define KTILES (KDIM / BK)   // 8
#define ALD 72               // smem row pitch in halves (64 + 8 pad)

#define ABYTES (BM * ALD * 2)        // 18432
#define BBYTES (BN * ALD * 2)        // 18432
#define STB (ABYTES + BBYTES)        // 36864
#define SMEM_TOTAL (3 * STB)         // 110592

// ------------------------------- device scratch -----------------------------
__device__ __half g_Xh[(size_t)NROWS * KDIM];
__device__ __half g_H1[(size_t)NROWS * KDIM];
__device__ __half g_W1t[KDIM * NDIM];   // W1^T: [n][k] fp16
__device__ __half g_W2t[KDIM * NDIM];
__device__ float  g_pool[NGRAPH * NDIM];
__device__ float  g_L1[GSIZE * NDIM];
__device__ float  g_L2[GSIZE * NDIM];
__device__ float  g_Wc[KDIM * OUTD];
__device__ float  g_bc[OUTD];

// ------------------------------- helpers ------------------------------------
__device__ __forceinline__ void cpasync16(void* smem_ptr, const void* gmem_ptr) {
    uint32_t s = (uint32_t)__cvta_generic_to_shared(smem_ptr);
    asm volatile("cp.async.cg.shared.global [%0], [%1], 16;\n" :: "r"(s), "l"(gmem_ptr));
}
__device__ __forceinline__ void cp_commit() {
    asm volatile("cp.async.commit_group;\n" ::: "memory");
}
__device__ __forceinline__ void cp_wait1() {
    asm volatile("cp.async.wait_group 1;\n" ::: "memory");
}
__device__ __forceinline__ void mma16816(float& c0, float& c1, float& c2, float& c3,
                                         uint32_t a0, uint32_t a1, uint32_t a2, uint32_t a3,
                                         uint32_t b0, uint32_t b1) {
    asm volatile(
        "mma.sync.aligned.m16n8k16.row.col.f32.f16.f16.f32 "
        "{%0,%1,%2,%3}, {%4,%5,%6,%7}, {%8,%9}, {%0,%1,%2,%3};\n"
        : "+f"(c0), "+f"(c1), "+f"(c2), "+f"(c3)
        : "r"(a0), "r"(a1), "r"(a2), "r"(a3), "r"(b0), "r"(b1));
}
__device__ __forceinline__ void ldsm_x4(uint32_t& r0, uint32_t& r1, uint32_t& r2, uint32_t& r3,
                                        uint32_t saddr) {
    asm volatile("ldmatrix.sync.aligned.m8n8.x4.shared.b16 {%0,%1,%2,%3}, [%4];"
                 : "=r"(r0), "=r"(r1), "=r"(r2), "=r"(r3) : "r"(saddr));
}
__device__ __forceinline__ uint32_t smem_u32(const void* p) {
    return (uint32_t)__cvta_generic_to_shared(p);
}

// ------------------------------- setup kernels ------------------------------
__global__ void conv_x_kernel(const float* __restrict__ x) {
    size_t i = ((size_t)blockIdx.x * blockDim.x + threadIdx.x) * 8;
    float4 v0 = *reinterpret_cast<const float4*>(x + i);
    float4 v1 = *reinterpret_cast<const float4*>(x + i + 4);
    __half2 h0 = __floats2half2_rn(v0.x, v0.y);
    __half2 h1 = __floats2half2_rn(v0.z, v0.w);
    __half2 h2 = __floats2half2_rn(v1.x, v1.y);
    __half2 h3 = __floats2half2_rn(v1.z, v1.w);
    uint4 packed = make_uint4(*reinterpret_cast<uint32_t*>(&h0), *reinterpret_cast<uint32_t*>(&h1),
                              *reinterpret_cast<uint32_t*>(&h2), *reinterpret_cast<uint32_t*>(&h3));
    *reinterpret_cast<uint4*>(g_Xh + i) = packed;
}

// out[n][k] = (half) W[k][n]
__global__ void convT_w_kernel(const float* __restrict__ W, int which) {
    __shared__ float t[32][33];
    __half* out = which ? g_W2t : g_W1t;
    int bx = blockIdx.x * 32, by = blockIdx.y * 32;
    #pragma unroll
    for (int i = 0; i < 32; i += 8)
        t[threadIdx.y + i][threadIdx.x] = W[(size_t)(by + threadIdx.y + i) * NDIM + bx + threadIdx.x];
    __syncthreads();
    #pragma unroll
    for (int i = 0; i < 32; i += 8)
        out[(size_t)(bx + threadIdx.y + i) * KDIM + by + threadIdx.x] =
            __float2half(t[threadIdx.x][threadIdx.y + i]);
}

__global__ void wc_kernel(const float* __restrict__ W3, const float* __restrict__ Wlin) {
    int k = blockIdx.x, c = threadIdx.x >> 5, lane = threadIdx.x & 31;
    float a = 0.f;
    for (int j = lane; j < KDIM; j += 32) a += W3[k * KDIM + j] * Wlin[j * OUTD + c];
    #pragma unroll
    for (int o = 16; o; o >>= 1) a += __shfl_xor_sync(0xffffffffu, a, o);
    if (lane == 0) g_Wc[k * OUTD + c] = a;
}

__global__ void bc_kernel(const float* __restrict__ b3, const float* __restrict__ Wlin,
                          const float* __restrict__ blin) {
    int c = threadIdx.x >> 5, lane = threadIdx.x & 31;
    float a = 0.f;
    for (int k = lane; k < KDIM; k += 32) a += b3[k] * Wlin[k * OUTD + c];
    #pragma unroll
    for (int o = 16; o; o >>= 1) a += __shfl_xor_sync(0xffffffffu, a, o);
    if (lane == 0) g_bc[c] = a + blin[c];
}

// ------------------------------- main GEMMs ---------------------------------
// MODE 1: H1 = relu(Xh @ W1 + b1); mtile 0 raw acc -> g_L1.
// MODE 2: pool[g] = colsum(relu(H1 @ W2 + b2)); mtile 0 raw acc -> g_L2.
template <int MODE>
__global__ void __launch_bounds__(256, 2) gemm_kernel(const float* __restrict__ bias) {
    extern __shared__ char smem[];
    const int tid  = threadIdx.x;
    const int lane = tid & 31;
    const int warp = tid >> 5;
    const int wm = warp >> 2;                // 0..1
    const int wn = warp & 3;                 // 0..3
    const int ntile = blockIdx.x;
    const int mtile = blockIdx.y;
    const size_t mbase = (size_t)mtile * BM;
    const int nbase = ntile * BN;

    const __half* __restrict__ A  = (MODE == 1) ? g_Xh  : g_H1;
    const __half* __restrict__ Bt = (MODE == 1) ? g_W1t : g_W2t;

    float acc[4][4][4];
    #pragma unroll
    for (int a = 0; a < 4; ++a)
        #pragma unroll
        for (int b = 0; b < 4; ++b)
            #pragma unroll
            for (int c = 0; c < 4; ++c) acc[a][b][c] = 0.f;

    const int lrow = lane & 15;              // ldmatrix row-select
    const int lkof = (lane >> 4) * 8;        // 0 or 8 halves

    auto load_stage = [&](int s, int kt) {
        const int k0 = kt * BK;
        char* as = smem + s * STB;
        char* bs = as + ABYTES;
        #pragma unroll
        for (int i = 0; i < 4; ++i) {
            int id = tid + 256 * i;
            int row = id >> 3, ch = id & 7;                 // 128 rows x 8 16B-chunks
            cpasync16(as + (row * ALD + ch * 8) * 2,
                      A + (mbase + row) * KDIM + k0 + ch * 8);
            cpasync16(bs + (row * ALD + ch * 8) * 2,
                      Bt + (size_t)(nbase + row) * KDIM + k0 + ch * 8);
        }
    };

    auto compute = [&](int s) {
        const char* as = smem + s * STB;
        const uint32_t a_u32 = smem_u32(as);
        const uint32_t b_u32 = a_u32 + ABYTES;
        #pragma unroll
        for (int ks = 0; ks < 4; ++ks) {
            const int kh = ks * 16;
            uint32_t af[4][4];
            #pragma unroll
            for (int mi = 0; mi < 4; ++mi) {
                int row = wm * 64 + mi * 16 + lrow;
                ldsm_x4(af[mi][0], af[mi][1], af[mi][2], af[mi][3],
                        a_u32 + (row * ALD + kh + lkof) * 2);
            }
            uint32_t bf[4][2];
            #pragma unroll
            for (int np = 0; np < 2; ++np) {
                int row = wn * 32 + np * 16 + lrow;
                ldsm_x4(bf[2 * np][0], bf[2 * np + 1][0],
                        bf[2 * np][1], bf[2 * np + 1][1],
                        b_u32 + (row * ALD + kh + lkof) * 2);
            }
            #pragma unroll
            for (int mi = 0; mi < 4; ++mi)
                #pragma unroll
                for (int ni = 0; ni < 4; ++ni)
                    mma16816(acc[mi][ni][0], acc[mi][ni][1], acc[mi][ni][2], acc[mi][ni][3],
                             af[mi][0], af[mi][1], af[mi][2], af[mi][3],
                             bf[ni][0], bf[ni][1]);
        }
    };

    load_stage(0, 0); cp_commit();
    load_stage(1, 1); cp_commit();

    for (int kt = 0; kt < KTILES; ++kt) {
        cp_wait1();
        __syncthreads();
        if (kt + 2 < KTILES) load_stage((kt + 2) % 3, kt + 2);
        cp_commit();
        compute(kt % 3);
    }

    // ------------------------------ epilogue --------------------------------
    if (MODE == 1) {
        #pragma unroll
        for (int mi = 0; mi < 4; ++mi) {
            int r0 = wm * 64 + mi * 16 + (lane >> 2);
            #pragma unroll
            for (int ni = 0; ni < 4; ++ni) {
                int c0 = wn * 32 + ni * 8 + ((lane & 3) << 1);
                int gc = nbase + c0;
                if (mtile == 0) {
                    g_L1[r0 * NDIM + gc]           = acc[mi][ni][0];
                    g_L1[r0 * NDIM + gc + 1]       = acc[mi][ni][1];
                    g_L1[(r0 + 8) * NDIM + gc]     = acc[mi][ni][2];
                    g_L1[(r0 + 8) * NDIM + gc + 1] = acc[mi][ni][3];
                }
                float bb0 = bias[gc], bb1 = bias[gc + 1];
                float v0 = fmaxf(acc[mi][ni][0] + bb0, 0.f);
                float v1 = fmaxf(acc[mi][ni][1] + bb1, 0.f);
                float v2 = fmaxf(acc[mi][ni][2] + bb0, 0.f);
                float v3 = fmaxf(acc[mi][ni][3] + bb1, 0.f);
                *reinterpret_cast<__half2*>(g_H1 + (mbase + r0) * NDIM + gc)     = __floats2half2_rn(v0, v1);
                *reinterpret_cast<__half2*>(g_H1 + (mbase + r0 + 8) * NDIM + gc) = __floats2half2_rn(v2, v3);
            }
        }
    } else {
        float cs0[4], cs1[4];
        #pragma unroll
        for (int ni = 0; ni < 4; ++ni) { cs0[ni] = 0.f; cs1[ni] = 0.f; }
        #pragma unroll
        for (int mi = 0; mi < 4; ++mi) {
            int r0 = wm * 64 + mi * 16 + (lane >> 2);
            #pragma unroll
            for (int ni = 0; ni < 4; ++ni) {
                int c0 = wn * 32 + ni * 8 + ((lane & 3) << 1);
                int gc = nbase + c0;
                if (mtile == 0) {
                    g_L2[r0 * NDIM + gc]           = acc[mi][ni][0];
                    g_L2[r0 * NDIM + gc + 1]       = acc[mi][ni][1];
                    g_L2[(r0 + 8) * NDIM + gc]     = acc[mi][ni][2];
                    g_L2[(r0 + 8) * NDIM + gc + 1] = acc[mi][ni][3];
                }
                float bb0 = bias[gc], bb1 = bias[gc + 1];
                cs0[ni] += fmaxf(acc[mi][ni][0] + bb0, 0.f) + fmaxf(acc[mi][ni][2] + bb0, 0.f);
                cs1[ni] += fmaxf(acc[mi][ni][1] + bb1, 0.f) + fmaxf(acc[mi][ni][3] + bb1, 0.f);
            }
        }
        #pragma unroll
        for (int ni = 0; ni < 4; ++ni) {
            #pragma unroll
            for (int o = 4; o <= 16; o <<= 1) {
                cs0[ni] += __shfl_xor_sync(0xffffffffu, cs0[ni], o);
                cs1[ni] += __shfl_xor_sync(0xffffffffu, cs1[ni], o);
            }
        }
        __syncthreads();
        float* cs = reinterpret_cast<float*>(smem);
        if (tid < BN) cs[tid] = 0.f;
        __syncthreads();
        if ((lane >> 2) == 0) {
            #pragma unroll
            for (int ni = 0; ni < 4; ++ni) {
                int c0 = wn * 32 + ni * 8 + ((lane & 3) << 1);
                atomicAdd(&cs[c0],     cs0[ni]);
                atomicAdd(&cs[c0 + 1], cs1[ni]);
            }
        }
        __syncthreads();
        if (tid < BN) g_pool[(size_t)mtile * NDIM + nbase + tid] = cs[tid];
    }
}

// ------------------------------- graph-0 fixups (parallel) ------------------
__global__ void fixup1_kernel(const float* __restrict__ b1) {
    int c = blockIdx.x;                  // 512 columns
    int r = threadIdx.x;                 // 128 rows
    float v = g_L1[r * NDIM + c];
    __shared__ float sred[4];
    float s = v;
    #pragma unroll
    for (int o = 16; o; o >>= 1) s += __shfl_xor_sync(0xffffffffu, s, o);
    if ((r & 31) == 0) sred[r >> 5] = s;
    __syncthreads();
    float S = sred[0] + sred[1] + sred[2] + sred[3];
    float out = (S + v) * (1.f / 129.f) + b1[c];
    g_H1[(size_t)r * NDIM + c] = __float2half(out > 0.f ? out : 0.f);
}

__global__ void fixup2_kernel(const float* __restrict__ b2) {
    int c = blockIdx.x;
    int r = threadIdx.x;
    float v = g_L2[r * NDIM + c];
    __shared__ float sred[4];
    float s = v;
    #pragma unroll
    for (int o = 16; o; o >>= 1) s += __shfl_xor_sync(0xffffffffu, s, o);
    if ((r & 31) == 0) sred[r >> 5] = s;
    __syncthreads();
    float S = sred[0] + sred[1] + sred[2] + sred[3];
    float val = (S + v) * (1.f / 129.f) + b2[c];
    float rel = val > 0.f ? val : 0.f;
    #pragma unroll
    for (int o = 16; o; o >>= 1) rel += __shfl_xor_sync(0xffffffffu, rel, o);
    if ((r & 31) == 0) sred[r >> 5] = rel;
    __syncthreads();
    if (r == 0) g_pool[c] = sred[0] + sred[1] + sred[2] + sred[3];
}

// ------------------------------- final projection ---------------------------
__global__ void final_kernel(float* __restrict__ out) {
    int g = blockIdx.x, c = threadIdx.x >> 5, lane = threadIdx.x & 31;
    float a = 0.f;
    for (int k = lane; k < KDIM; k += 32)
        a += g_pool[(size_t)g * NDIM + k] * g_Wc[k * OUTD + c];
    #pragma unroll
    for (int o = 16; o; o >>= 1) a += __shfl_xor_sync(0xffffffffu, a, o);
    if (lane == 0) out[g * OUTD + c] = a * (1.f / (float)GSIZE) + g_bc[c];
}

// ------------------------------- launch -------------------------------------
extern "C" void kernel_launch(void* const* d_in, const int* in_sizes, int n_in,
                              void* d_out, int out_size) {
    const float* x    = (const float*)d_in[0];
    const float* W1   = (const float*)d_in[1];
    const float* b1   = (const float*)d_in[2];
    const float* W2   = (const float*)d_in[3];
    const float* b2   = (const float*)d_in[4];
    const float* W3   = (const float*)d_in[5];
    const float* b3   = (const float*)d_in[6];
    const float* Wlin = (const float*)d_in[7];
    const float* blin = (const float*)d_in[8];
    float* out = (float*)d_out;

    cudaFuncSetAttribute(gemm_kernel<1>, cudaFuncAttributeMaxDynamicSharedMemorySize, SMEM_TOTAL);
    cudaFuncSetAttribute(gemm_kernel<2>, cudaFuncAttributeMaxDynamicSharedMemorySize, SMEM_TOTAL);

    dim3 grid(NDIM / BN, NROWS / BM);    // (4, 512)

    conv_x_kernel<<<(int)(((size_t)NROWS * KDIM) / (256 * 8)), 256>>>(x);   // 1
    convT_w_kernel<<<dim3(16, 16), dim3(32, 8)>>>(W1, 0);                   // 2
    convT_w_kernel<<<dim3(16, 16), dim3(32, 8)>>>(W2, 1);                   // 3
    gemm_kernel<1><<<grid, 256, SMEM_TOTAL>>>(b1);                          // 4  <- ncu
    fixup1_kernel<<<NDIM, GSIZE>>>(b1);                                     // 5
    gemm_kernel<2><<<grid, 256, SMEM_TOTAL>>>(b2);                          // 6
    bc_kernel<<<1, 320>>>(b3, Wlin, blin);                                  // 7
    wc_kernel<<<KDIM, 320>>>(W3, Wlin);                                     // 8
    fixup2_kernel<<<NDIM, GSIZE>>>(b2);                                     // 9
    final_kernel<<<NGRAPH, 320>>>(out);                                     // 10
}

// round 9
// speedup vs baseline: 1.2778x; 1.0314x over previous
#include <cuda_runtime.h>
#include <cuda_fp16.h>
#include <cstdint>

// ---------------------------------------------------------------------------
// GCN_simple: layer3+meanpool collapse analytically; layers 1-2 are dense
// GEMMs (identity propagation except graph 0, fixed by parallel fixups).
// mma.sync HMMA pipeline (tcgen05 rejected by compute_103 virtual target).
// R8: 512-thread CTAs, 32x32 warp tiles -> 32 warps/SM (2 CTAs) for latency
// hiding; fully unrolled k-loop with constant stage offsets.
// ---------------------------------------------------------------------------

#define NROWS 65536      // BATCH * N_NODES
#define KDIM  512
#define NDIM  512
#define NGRAPH 512
#define GSIZE  128
#define OUTD   10

#define BM 128
#define BN 128
#define BK 64
#define KTILES (KDIM / BK)   // 8
#define ALD 72               // smem row pitch in halves (64 + 8 pad)

#define ABYTES (BM * ALD * 2)        // 18432
#define BBYTES (BN * ALD * 2)        // 18432
#define STB (ABYTES + BBYTES)        // 36864
#define SMEM_TOTAL (3 * STB)         // 110592

#define NTHREADS 512

// ------------------------------- device scratch -----------------------------
__device__ __half g_Xh[(size_t)NROWS * KDIM];
__device__ __half g_H1[(size_t)NROWS * KDIM];
__device__ __half g_W1t[KDIM * NDIM];   // W1^T: [n][k] fp16
__device__ __half g_W2t[KDIM * NDIM];
__device__ float  g_pool[NGRAPH * NDIM];
__device__ float  g_L1[GSIZE * NDIM];
__device__ float  g_L2[GSIZE * NDIM];
__device__ float  g_Wc[KDIM * OUTD];
__device__ float  g_bc[OUTD];

// ------------------------------- helpers ------------------------------------
__device__ __forceinline__ void cpasync16(void* smem_ptr, const void* gmem_ptr) {
    uint32_t s = (uint32_t)__cvta_generic_to_shared(smem_ptr);
    asm volatile("cp.async.cg.shared.global [%0], [%1], 16;\n" :: "r"(s), "l"(gmem_ptr));
}
__device__ __forceinline__ void cp_commit() {
    asm volatile("cp.async.commit_group;\n" ::: "memory");
}
__device__ __forceinline__ void cp_wait1() {
    asm volatile("cp.async.wait_group 1;\n" ::: "memory");
}
__device__ __forceinline__ void mma16816(float& c0, float& c1, float& c2, float& c3,
                                         uint32_t a0, uint32_t a1, uint32_t a2, uint32_t a3,
                                         uint32_t b0, uint32_t b1) {
    asm volatile(
        "mma.sync.aligned.m16n8k16.row.col.f32.f16.f16.f32 "
        "{%0,%1,%2,%3}, {%4,%5,%6,%7}, {%8,%9}, {%0,%1,%2,%3};\n"
        : "+f"(c0), "+f"(c1), "+f"(c2), "+f"(c3)
        : "r"(a0), "r"(a1), "r"(a2), "r"(a3), "r"(b0), "r"(b1));
}
__device__ __forceinline__ void ldsm_x4(uint32_t& r0, uint32_t& r1, uint32_t& r2, uint32_t& r3,
                                        uint32_t saddr) {
    asm volatile("ldmatrix.sync.aligned.m8n8.x4.shared.b16 {%0,%1,%2,%3}, [%4];"
                 : "=r"(r0), "=r"(r1), "=r"(r2), "=r"(r3) : "r"(saddr));
}
__device__ __forceinline__ uint32_t smem_u32(const void* p) {
    return (uint32_t)__cvta_generic_to_shared(p);
}

// ------------------------------- setup kernels ------------------------------
__global__ void conv_x_kernel(const float* __restrict__ x) {
    size_t i = ((size_t)blockIdx.x * blockDim.x + threadIdx.x) * 8;
    float4 v0 = *reinterpret_cast<const float4*>(x + i);
    float4 v1 = *reinterpret_cast<const float4*>(x + i + 4);
    __half2 h0 = __floats2half2_rn(v0.x, v0.y);
    __half2 h1 = __floats2half2_rn(v0.z, v0.w);
    __half2 h2 = __floats2half2_rn(v1.x, v1.y);
    __half2 h3 = __floats2half2_rn(v1.z, v1.w);
    uint4 packed = make_uint4(*reinterpret_cast<uint32_t*>(&h0), *reinterpret_cast<uint32_t*>(&h1),
                              *reinterpret_cast<uint32_t*>(&h2), *reinterpret_cast<uint32_t*>(&h3));
    *reinterpret_cast<uint4*>(g_Xh + i) = packed;
}

// out[n][k] = (half) W[k][n]
__global__ void convT_w_kernel(const float* __restrict__ W, int which) {
    __shared__ float t[32][33];
    __half* out = which ? g_W2t : g_W1t;
    int bx = blockIdx.x * 32, by = blockIdx.y * 32;
    #pragma unroll
    for (int i = 0; i < 32; i += 8)
        t[threadIdx.y + i][threadIdx.x] = W[(size_t)(by + threadIdx.y + i) * NDIM + bx + threadIdx.x];
    __syncthreads();
    #pragma unroll
    for (int i = 0; i < 32; i += 8)
        out[(size_t)(bx + threadIdx.y + i) * KDIM + by + threadIdx.x] =
            __float2half(t[threadIdx.x][threadIdx.y + i]);
}

__global__ void wc_kernel(const float* __restrict__ W3, const float* __restrict__ Wlin) {
    int k = blockIdx.x, c = threadIdx.x >> 5, lane = threadIdx.x & 31;
    float a = 0.f;
    for (int j = lane; j < KDIM; j += 32) a += W3[k * KDIM + j] * Wlin[j * OUTD + c];
    #pragma unroll
    for (int o = 16; o; o >>= 1) a += __shfl_xor_sync(0xffffffffu, a, o);
    if (lane == 0) g_Wc[k * OUTD + c] = a;
}

__global__ void bc_kernel(const float* __restrict__ b3, const float* __restrict__ Wlin,
                          const float* __restrict__ blin) {
    int c = threadIdx.x >> 5, lane = threadIdx.x & 31;
    float a = 0.f;
    for (int k = lane; k < KDIM; k += 32) a += b3[k] * Wlin[k * OUTD + c];
    #pragma unroll
    for (int o = 16; o; o >>= 1) a += __shfl_xor_sync(0xffffffffu, a, o);
    if (lane == 0) g_bc[c] = a + blin[c];
}

// ------------------------------- main GEMMs ---------------------------------
// 512 threads, 16 warps as 4x4 grid of 32x32 warp tiles over 128x128 CTA tile.
// MODE 1: H1 = relu(Xh @ W1 + b1); mtile 0 raw acc -> g_L1.
// MODE 2: pool[g] = colsum(relu(H1 @ W2 + b2)); mtile 0 raw acc -> g_L2.
template <int MODE>
__global__ void __launch_bounds__(NTHREADS, 2) gemm_kernel(const float* __restrict__ bias) {
    extern __shared__ char smem[];
    const int tid  = threadIdx.x;
    const int lane = tid & 31;
    const int warp = tid >> 5;
    const int wm = warp >> 2;                // 0..3  (32-row strip)
    const int wn = warp & 3;                 // 0..3  (32-col strip)
    const int ntile = blockIdx.x;
    const int mtile = blockIdx.y;
    const size_t mbase = (size_t)mtile * BM;
    const int nbase = ntile * BN;

    const __half* __restrict__ A  = (MODE == 1) ? g_Xh  : g_H1;
    const __half* __restrict__ Bt = (MODE == 1) ? g_W1t : g_W2t;

    float acc[2][4][4];
    #pragma unroll
    for (int a = 0; a < 2; ++a)
        #pragma unroll
        for (int b = 0; b < 4; ++b)
            #pragma unroll
            for (int c = 0; c < 4; ++c) acc[a][b][c] = 0.f;

    const int lrow = lane & 15;              // ldmatrix row-select
    const int lkof = (lane >> 4) * 8;        // 0 or 8 halves

    auto load_stage = [&](int s, int kt) {
        const int k0 = kt * BK;
        char* as = smem + s * STB;
        char* bs = as + ABYTES;
        #pragma unroll
        for (int i = 0; i < 2; ++i) {
            int id = tid + NTHREADS * i;
            int row = id >> 3, ch = id & 7;                 // 128 rows x 8 16B-chunks
            cpasync16(as + (row * ALD + ch * 8) * 2,
                      A + (mbase + row) * KDIM + k0 + ch * 8);
            cpasync16(bs + (row * ALD + ch * 8) * 2,
                      Bt + (size_t)(nbase + row) * KDIM + k0 + ch * 8);
        }
    };

    auto compute = [&](int s) {
        const char* as = smem + s * STB;
        const uint32_t a_u32 = smem_u32(as);
        const uint32_t b_u32 = a_u32 + ABYTES;
        #pragma unroll
        for (int ks = 0; ks < 4; ++ks) {
            const int kh = ks * 16;
            uint32_t af[2][4];
            #pragma unroll
            for (int mi = 0; mi < 2; ++mi) {
                int row = wm * 32 + mi * 16 + lrow;
                ldsm_x4(af[mi][0], af[mi][1], af[mi][2], af[mi][3],
                        a_u32 + (row * ALD + kh + lkof) * 2);
            }
            uint32_t bf[4][2];
            #pragma unroll
            for (int np = 0; np < 2; ++np) {
                int row = wn * 32 + np * 16 + lrow;
                ldsm_x4(bf[2 * np][0], bf[2 * np + 1][0],
                        bf[2 * np][1], bf[2 * np + 1][1],
                        b_u32 + (row * ALD + kh + lkof) * 2);
            }
            #pragma unroll
            for (int mi = 0; mi < 2; ++mi)
                #pragma unroll
                for (int ni = 0; ni < 4; ++ni)
                    mma16816(acc[mi][ni][0], acc[mi][ni][1], acc[mi][ni][2], acc[mi][ni][3],
                             af[mi][0], af[mi][1], af[mi][2], af[mi][3],
                             bf[ni][0], bf[ni][1]);
        }
    };

    load_stage(0, 0); cp_commit();
    load_stage(1, 1); cp_commit();

    #pragma unroll
    for (int kt = 0; kt < KTILES; ++kt) {
        cp_wait1();
        __syncthreads();
        if (kt + 2 < KTILES) load_stage((kt + 2) % 3, kt + 2);
        cp_commit();
        compute(kt % 3);
    }

    // ------------------------------ epilogue --------------------------------
    if (MODE == 1) {
        #pragma unroll
        for (int mi = 0; mi < 2; ++mi) {
            int r0 = wm * 32 + mi * 16 + (lane >> 2);
            #pragma unroll
            for (int ni = 0; ni < 4; ++ni) {
                int c0 = wn * 32 + ni * 8 + ((lane & 3) << 1);
                int gc = nbase + c0;
                if (mtile == 0) {
                    g_L1[r0 * NDIM + gc]           = acc[mi][ni][0];
                    g_L1[r0 * NDIM + gc + 1]       = acc[mi][ni][1];
                    g_L1[(r0 + 8) * NDIM + gc]     = acc[mi][ni][2];
                    g_L1[(r0 + 8) * NDIM + gc + 1] = acc[mi][ni][3];
                }
                float bb0 = bias[gc], bb1 = bias[gc + 1];
                float v0 = fmaxf(acc[mi][ni][0] + bb0, 0.f);
                float v1 = fmaxf(acc[mi][ni][1] + bb1, 0.f);
                float v2 = fmaxf(acc[mi][ni][2] + bb0, 0.f);
                float v3 = fmaxf(acc[mi][ni][3] + bb1, 0.f);
                *reinterpret_cast<__half2*>(g_H1 + (mbase + r0) * NDIM + gc)     = __floats2half2_rn(v0, v1);
                *reinterpret_cast<__half2*>(g_H1 + (mbase + r0 + 8) * NDIM + gc) = __floats2half2_rn(v2, v3);
            }
        }
    } else {
        float cs0[4], cs1[4];
        #pragma unroll
        for (int ni = 0; ni < 4; ++ni) { cs0[ni] = 0.f; cs1[ni] = 0.f; }
        #pragma unroll
        for (int mi = 0; mi < 2; ++mi) {
            int r0 = wm * 32 + mi * 16 + (lane >> 2);
            #pragma unroll
            for (int ni = 0; ni < 4; ++ni) {
                int c0 = wn * 32 + ni * 8 + ((lane & 3) << 1);
                int gc = nbase + c0;
                if (mtile == 0) {
                    g_L2[r0 * NDIM + gc]           = acc[mi][ni][0];
                    g_L2[r0 * NDIM + gc + 1]       = acc[mi][ni][1];
                    g_L2[(r0 + 8) * NDIM + gc]     = acc[mi][ni][2];
                    g_L2[(r0 + 8) * NDIM + gc + 1] = acc[mi][ni][3];
                }
                float bb0 = bias[gc], bb1 = bias[gc + 1];
                cs0[ni] += fmaxf(acc[mi][ni][0] + bb0, 0.f) + fmaxf(acc[mi][ni][2] + bb0, 0.f);
                cs1[ni] += fmaxf(acc[mi][ni][1] + bb1, 0.f) + fmaxf(acc[mi][ni][3] + bb1, 0.f);
            }
        }
        // reduce over the 8 lanes sharing (lane & 3): sums this warp's 32 rows
        #pragma unroll
        for (int ni = 0; ni < 4; ++ni) {
            #pragma unroll
            for (int o = 4; o <= 16; o <<= 1) {
                cs0[ni] += __shfl_xor_sync(0xffffffffu, cs0[ni], o);
                cs1[ni] += __shfl_xor_sync(0xffffffffu, cs1[ni], o);
            }
        }
        __syncthreads();
        float* cs = reinterpret_cast<float*>(smem);
        if (tid < BN) cs[tid] = 0.f;
        __syncthreads();
        if ((lane >> 2) == 0) {           // lanes 0..3: 4 wm-warps add into each column
            #pragma unroll
            for (int ni = 0; ni < 4; ++ni) {
                int c0 = wn * 32 + ni * 8 + ((lane & 3) << 1);
                atomicAdd(&cs[c0],     cs0[ni]);
                atomicAdd(&cs[c0 + 1], cs1[ni]);
            }
        }
        __syncthreads();
        if (tid < BN) g_pool[(size_t)mtile * NDIM + nbase + tid] = cs[tid];
    }
}

// ------------------------------- graph-0 fixups (parallel) ------------------
__global__ void fixup1_kernel(const float* __restrict__ b1) {
    int c = blockIdx.x;                  // 512 columns
    int r = threadIdx.x;                 // 128 rows
    float v = g_L1[r * NDIM + c];
    __shared__ float sred[4];
    float s = v;
    #pragma unroll
    for (int o = 16; o; o >>= 1) s += __shfl_xor_sync(0xffffffffu, s, o);
    if ((r & 31) == 0) sred[r >> 5] = s;
    __syncthreads();
    float S = sred[0] + sred[1] + sred[2] + sred[3];
    float out = (S + v) * (1.f / 129.f) + b1[c];
    g_H1[(size_t)r * NDIM + c] = __float2half(out > 0.f ? out : 0.f);
}

__global__ void fixup2_kernel(const float* __restrict__ b2) {
    int c = blockIdx.x;
    int r = threadIdx.x;
    float v = g_L2[r * NDIM + c];
    __shared__ float sred[4];
    float s = v;
    #pragma unroll
    for (int o = 16; o; o >>= 1) s += __shfl_xor_sync(0xffffffffu, s, o);
    if ((r & 31) == 0) sred[r >> 5] = s;
    __syncthreads();
    float S = sred[0] + sred[1] + sred[2] + sred[3];
    float val = (S + v) * (1.f / 129.f) + b2[c];
    float rel = val > 0.f ? val : 0.f;
    #pragma unroll
    for (int o = 16; o; o >>= 1) rel += __shfl_xor_sync(0xffffffffu, rel, o);
    if ((r & 31) == 0) sred[r >> 5] = rel;
    __syncthreads();
    if (r == 0) g_pool[c] = sred[0] + sred[1] + sred[2] + sred[3];
}

// ------------------------------- final projection ---------------------------
__global__ void final_kernel(float* __restrict__ out) {
    int g = blockIdx.x, c = threadIdx.x >> 5, lane = threadIdx.x & 31;
    float a = 0.f;
    for (int k = lane; k < KDIM; k += 32)
        a += g_pool[(size_t)g * NDIM + k] * g_Wc[k * OUTD + c];
    #pragma unroll
    for (int o = 16; o; o >>= 1) a += __shfl_xor_sync(0xffffffffu, a, o);
    if (lane == 0) out[g * OUTD + c] = a * (1.f / (float)GSIZE) + g_bc[c];
}

// ------------------------------- launch -------------------------------------
extern "C" void kernel_launch(void* const* d_in, const int* in_sizes, int n_in,
                              void* d_out, int out_size) {
    const float* x    = (const float*)d_in[0];
    const float* W1   = (const float*)d_in[1];
    const float* b1   = (const float*)d_in[2];
    const float* W2   = (const float*)d_in[3];
    const float* b2   = (const float*)d_in[4];
    const float* W3   = (const float*)d_in[5];
    const float* b3   = (const float*)d_in[6];
    const float* Wlin = (const float*)d_in[7];
    const float* blin = (const float*)d_in[8];
    float* out = (float*)d_out;

    cudaFuncSetAttribute(gemm_kernel<1>, cudaFuncAttributeMaxDynamicSharedMemorySize, SMEM_TOTAL);
    cudaFuncSetAttribute(gemm_kernel<2>, cudaFuncAttributeMaxDynamicSharedMemorySize, SMEM_TOTAL);

    dim3 grid(NDIM / BN, NROWS / BM);    // (4, 512)

    conv_x_kernel<<<(int)(((size_t)NROWS * KDIM) / (256 * 8)), 256>>>(x);   // 1
    convT_w_kernel<<<dim3(16, 16), dim3(32, 8)>>>(W1, 0);                   // 2
    convT_w_kernel<<<dim3(16, 16), dim3(32, 8)>>>(W2, 1);                   // 3
    gemm_kernel<1><<<grid, NTHREADS, SMEM_TOTAL>>>(b1);                     // 4  <- ncu
    fixup1_kernel<<<NDIM, GSIZE>>>(b1);                                     // 5
    gemm_kernel<2><<<grid, NTHREADS, SMEM_TOTAL>>>(b2);                     // 6
    bc_kernel<<<1, 320>>>(b3, Wlin, blin);                                  // 7
    wc_kernel<<<KDIM, 320>>>(W3, Wlin);                                     // 8
    fixup2_kernel<<<NDIM, GSIZE>>>(b2);                                     // 9
    final_kernel<<<NGRAPH, 320>>>(out);                                     // 10
}